// round 3
// baseline (speedup 1.0000x reference)
#include <cuda_runtime.h>
#include <math_constants.h>

// Shape: B = 65536 rows, C = 1000 classes (fp32 output + target).
#define NCLS    1000
#define TPB     256
#define NW      (TPB / 32)
#define MAXGRID 8192

// Per-CTA partial sums (deterministic; no fp atomics).
__device__ double g_part[MAXGRID];

__device__ __forceinline__ float warp_max(float v) {
    #pragma unroll
    for (int o = 16; o > 0; o >>= 1) v = fmaxf(v, __shfl_xor_sync(0xffffffffu, v, o));
    return v;
}
__device__ __forceinline__ float warp_sum(float v) {
    #pragma unroll
    for (int o = 16; o > 0; o >>= 1) v += __shfl_xor_sync(0xffffffffu, v, o);
    return v;
}
__device__ __forceinline__ double warp_sum_d(double v) {
    #pragma unroll
    for (int o = 16; o > 0; o >>= 1) v += __shfl_xor_sync(0xffffffffu, v, o);
    return v;
}

struct Sh {
    float m[NW];
    float a[NW], b[NW], c[NW];
    float l[NW], n[NW];
};

// Process one row held in registers. ALL threads of the CTA must call this
// (3 __syncthreads inside). Every thread returns the row loss.
__device__ __forceinline__ float process_row(const float o[4], const float t[4],
                                             bool active, Sh* sh, int wid, int lane) {
    // ---- pass 1: row max (all-threads-get-result: 1 barrier) ----
    float lm = fmaxf(fmaxf(o[0], o[1]), fmaxf(o[2], o[3]));   // inactive: -inf
    lm = warp_max(lm);
    if (lane == 0) sh->m[wid] = lm;
    __syncthreads();
    const float m = warp_max((lane < NW) ? sh->m[lane] : -CUDART_INF_F);

    // ---- pass 2: negative-set sums ----
    float e[4];
    float s = 0.0f, tn = 0.0f, an = 0.0f;
    #pragma unroll
    for (int i = 0; i < 4; i++) {
        e[i] = __expf(o[i] - m);                // inactive: exp(-inf)=0
        if (active && t[i] <= 0.5f) {
            s  += e[i];
            tn += t[i];
            an += t[i] * o[i];
        }
    }
    s = warp_sum(s); tn = warp_sum(tn); an = warp_sum(an);
    if (lane == 0) { sh->a[wid] = s; sh->b[wid] = tn; sh->c[wid] = an; }
    __syncthreads();
    const float Sneg = warp_sum((lane < NW) ? sh->a[lane] : 0.0f);
    const float Tneg = warp_sum((lane < NW) ? sh->b[lane] : 0.0f);
    const float Aneg = warp_sum((lane < NW) ? sh->c[lane] : 0.0f);

    // ---- pass 3: positive losses ----
    float L = 0.0f, N = 0.0f;
    if (active) {
        #pragma unroll
        for (int i = 0; i < 4; i++) {
            if (t[i] > 0.5f) {
                float lse = m + __logf(Sneg + e[i]);
                L += (Tneg + t[i]) * lse - Aneg - t[i] * o[i];
                N += 1.0f;
            }
        }
    }
    L = warp_sum(L); N = warp_sum(N);
    if (lane == 0) { sh->l[wid] = L; sh->n[wid] = N; }
    __syncthreads();
    L = warp_sum((lane < NW) ? sh->l[lane] : 0.0f);
    N = warp_sum((lane < NW) ? sh->n[lane] : 0.0f);

    if (N > 0.0f) return L / N;
    return Tneg * (m + __logf(Sneg)) - Aneg;     // no-positive fallback
}

__device__ __forceinline__ void load_row(const float* __restrict__ outp,
                                         const float* __restrict__ tgt,
                                         int row, int tid, float o[4], float t[4]) {
    const float4 ov = reinterpret_cast<const float4*>(outp + (size_t)row * NCLS)[tid];
    const float4 tv = reinterpret_cast<const float4*>(tgt  + (size_t)row * NCLS)[tid];
    o[0] = ov.x; o[1] = ov.y; o[2] = ov.z; o[3] = ov.w;
    t[0] = tv.x; t[1] = tv.y; t[2] = tv.z; t[3] = tv.w;
}

__global__ __launch_bounds__(TPB)
void mvce_main(const float* __restrict__ outp, const float* __restrict__ tgt,
               double* __restrict__ part, int B) {
    __shared__ Sh sh;
    const int tid  = threadIdx.x;
    const int wid  = tid >> 5;
    const int lane = tid & 31;
    const bool active = (tid < NCLS / 4);       // 250 active, 16B each
    const int stride = gridDim.x;

    float oA[4], tA[4], oB[4], tB[4];
    #pragma unroll
    for (int i = 0; i < 4; i++) {
        oA[i] = oB[i] = -CUDART_INF_F;
        tA[i] = tB[i] = 0.0f;
    }

    double acc = 0.0;
    int row = blockIdx.x;
    if (active && row < B) load_row(outp, tgt, row, tid, oA, tA);

    // Double-buffered grid-stride: next row's loads in flight during
    // current row's 3 reduction barriers -> continuous DRAM streaming.
    for (; row < B; row += 2 * stride) {
        const int rB = row + stride;
        if (active && rB < B) load_row(outp, tgt, rB, tid, oB, tB);
        acc += (double)process_row(oA, tA, active, &sh, wid, lane);
        if (rB < B) {
            const int rA = rB + stride;
            if (active && rA < B) load_row(outp, tgt, rA, tid, oA, tA);
            acc += (double)process_row(oB, tB, active, &sh, wid, lane);
        }
    }

    if (tid == 0) part[blockIdx.x] = acc;
}

__global__ __launch_bounds__(TPB)
void mvce_final(const double* __restrict__ part, float* __restrict__ out,
                int n, int B) {
    const int tid = threadIdx.x;
    double a = 0.0;
    for (int i = tid; i < n; i += TPB) a += part[i];
    a = warp_sum_d(a);
    __shared__ double sh[NW];
    if ((tid & 31) == 0) sh[tid >> 5] = a;
    __syncthreads();
    if (tid < 32) {
        double v = (tid < NW) ? sh[tid] : 0.0;
        v = warp_sum_d(v);
        if (tid == 0) out[0] = (float)(v / (double)B);
    }
}

extern "C" void kernel_launch(void* const* d_in, const int* in_sizes, int n_in,
                              void* d_out, int out_size) {
    const float* output = (const float*)d_in[0];
    const float* target = (const float*)d_in[1];
    float* out = (float*)d_out;

    const int B = in_sizes[0] / NCLS;

    int dev = 0;
    cudaGetDevice(&dev);
    int sms = 148;
    cudaDeviceGetAttribute(&sms, cudaDevAttrMultiProcessorCount, dev);
    int nb = 0;
    cudaOccupancyMaxActiveBlocksPerMultiprocessor(&nb, mvce_main, TPB, 0);
    if (nb < 1) nb = 1;

    int grid = sms * nb;                 // exactly one wave -> perfect balance
    if (grid > MAXGRID) grid = MAXGRID;
    if (grid > B) grid = B;
    if (grid < 1) grid = 1;

    double* part;
    cudaGetSymbolAddress((void**)&part, g_part);

    mvce_main<<<grid, TPB>>>(output, target, part, B);
    mvce_final<<<1, TPB>>>(part, out, grid, B);
}

// round 7
// speedup vs baseline: 1.4778x; 1.4778x over previous
#include <cuda_runtime.h>

// Shape: B = 65536 rows, C = 1000 fp32 classes. 250 float4 per row.
#define NCLS    1000
#define NF4     250
#define TPB     32
#define MAXGRID 4096

__device__ double   g_part[MAXGRID];
__device__ unsigned g_ticket = 0;

__device__ __forceinline__ float warp_sum(float v) {
    #pragma unroll
    for (int o = 16; o > 0; o >>= 1) v += __shfl_xor_sync(0xffffffffu, v, o);
    return v;
}
__device__ __forceinline__ double warp_sum_d(double v) {
    #pragma unroll
    for (int o = 16; o > 0; o >>= 1) v += __shfl_xor_sync(0xffffffffu, v, o);
    return v;
}

// Pass-A per-element accumulate (negative-set stats + positive-side sums).
__device__ __forceinline__ void elemA(float e, float t, float o,
                                      float& s, float& tn, float& an,
                                      float& ap, float& np) {
    if (t <= 0.5f) {            // negative (and zero-padded tail: e=0,t=0)
        s  += e;
        tn += t;
        an  = fmaf(t, o, an);
    } else {                    // positive
        ap  = fmaf(t, o, ap);
        np += 1.0f;
    }
}

__global__ void __launch_bounds__(TPB)
mvce_warp(const float* __restrict__ outp, const float* __restrict__ tgt,
          float* __restrict__ result, int B, int nwarps) {
    const int lane = threadIdx.x;
    const int gw   = blockIdx.x;

    double acc = 0.0;

    for (int row = gw; row < B; row += nwarps) {
        const float4* __restrict__ o4 =
            reinterpret_cast<const float4*>(outp + (size_t)row * NCLS);
        const float4* __restrict__ t4 =
            reinterpret_cast<const float4*>(tgt  + (size_t)row * NCLS);

        float4 ev[8], tv[8];                    // e = exp(o), t  (register-resident)
        float s = 0.f, tn = 0.f, an = 0.f, ap = 0.f, np = 0.f;

        // ---- single data pass: load, exp, accumulate; keep e,t in regs ----
        #pragma unroll
        for (int k = 0; k < 8; k++) {
            const int  idx   = k * 32 + lane;
            const bool valid = (k < 7) || (lane < 26);   // 250 float4/row
            float4 ov = valid ? o4[idx] : make_float4(0.f, 0.f, 0.f, 0.f);
            float4 tt = valid ? t4[idx] : make_float4(0.f, 0.f, 0.f, 0.f);
            float4 e;
            e.x = valid ? __expf(ov.x) : 0.f;
            e.y = valid ? __expf(ov.y) : 0.f;
            e.z = valid ? __expf(ov.z) : 0.f;
            e.w = valid ? __expf(ov.w) : 0.f;
            elemA(e.x, tt.x, ov.x, s, tn, an, ap, np);
            elemA(e.y, tt.y, ov.y, s, tn, an, ap, np);
            elemA(e.z, tt.z, ov.z, s, tn, an, ap, np);
            elemA(e.w, tt.w, ov.w, s, tn, an, ap, np);
            ev[k] = e; tv[k] = tt;
        }

        // ---- warp butterfly: Sneg, Tneg, Aneg (no barriers, all lanes get total) ----
        const float Sneg = warp_sum(s);
        const float Tneg = warp_sum(tn);
        const float Aneg = warp_sum(an);

        // ---- positive LSE terms: sum_p (Tneg + t_p) * log(Sneg + e_p) ----
        float L = 0.f;
        #pragma unroll
        for (int k = 0; k < 8; k++) {
            if (tv[k].x > 0.5f) L = fmaf(Tneg + tv[k].x, __logf(Sneg + ev[k].x), L);
            if (tv[k].y > 0.5f) L = fmaf(Tneg + tv[k].y, __logf(Sneg + ev[k].y), L);
            if (tv[k].z > 0.5f) L = fmaf(Tneg + tv[k].z, __logf(Sneg + ev[k].z), L);
            if (tv[k].w > 0.5f) L = fmaf(Tneg + tv[k].w, __logf(Sneg + ev[k].w), L);
        }

        const float Lt  = warp_sum(L);
        const float apT = warp_sum(ap);
        const float npT = warp_sum(np);

        float r;
        if (npT > 0.0f) {
            // sum_p loss_p = Lt - np*Aneg - sum_p t_p*o_p;  averaged over positives
            r = (Lt - npT * Aneg - apT) / npT;
        } else {
            r = Tneg * __logf(Sneg) - Aneg;   // no-positive fallback
        }
        acc += (double)r;
    }

    // ---- per-warp partial + fused deterministic fan-in ----
    if (lane == 0) g_part[gw] = acc;

    unsigned isLast = 0;
    if (lane == 0) {
        __threadfence();
        if (atomicAdd(&g_ticket, 1u) == (unsigned)(gridDim.x - 1)) isLast = 1;
    }
    isLast = __shfl_sync(0xffffffffu, isLast, 0);

    if (isLast) {
        __threadfence();                       // gpu-scope: flush L1, see all partials
        const int n = gridDim.x;
        double a = 0.0;
        for (int i = lane; i < n; i += 32)     // fixed order -> deterministic
            a += g_part[i];
        a = warp_sum_d(a);
        if (lane == 0) {
            result[0] = (float)(a / (double)B);
            g_ticket = 0;                      // reset for next graph replay
        }
    }
}

extern "C" void kernel_launch(void* const* d_in, const int* in_sizes, int n_in,
                              void* d_out, int out_size) {
    const float* output = (const float*)d_in[0];
    const float* target = (const float*)d_in[1];
    float* out = (float*)d_out;

    const int B = in_sizes[0] / NCLS;

    int grid = 2048;                 // 32 rows per warp at B=65536
    if (grid > B) grid = B;
    if (grid > MAXGRID) grid = MAXGRID;
    if (grid < 1) grid = 1;

    mvce_warp<<<grid, TPB>>>(output, target, out, B, grid);
}